// round 1
// baseline (speedup 1.0000x reference)
#include <cuda_runtime.h>
#include <cstdint>
#include <cstddef>

// ---------------------------------------------------------------------------
// GAU denoising model, fp32 baseline.
// B=16, IMG=128, P=8 -> L=256 tokens, PD=192, H=768, E=1536, K=128, NL=24.
// Rows = B*L = 4096.
// ---------------------------------------------------------------------------

#define NB      16
#define LTOK    256
#define HD      768
#define ED      1536
#define KDIM    128
#define UVQK    3328      // 2E + 2K
#define ROWS    4096      // NB*LTOK
#define NLAYERS 24
#define PDIM    192

// Scratch (device globals; no allocation allowed)
__device__ float g_h   [(size_t)ROWS * HD];     // residual stream
__device__ float g_xn  [(size_t)ROWS * HD];     // rmsnorm output
__device__ float g_uvqk[(size_t)ROWS * UVQK];   // fused projection out
__device__ float g_attn[(size_t)ROWS * LTOK];   // softmax(qk^T)
__device__ float g_av  [(size_t)ROWS * ED];     // attn @ v (then * u)

// ---------------------------------------------------------------------------
// Patchify + patch_W GEMM + time-embedding bias.  One block per token row.
// ---------------------------------------------------------------------------
__global__ void patch_kernel(const float* __restrict__ x,
                             const int*   __restrict__ t_idx,
                             const float* __restrict__ pw,
                             const float* __restrict__ temb) {
    int r = blockIdx.x;                 // 0..4095
    int b = r >> 8, l = r & 255;
    int gy = l >> 4, gx = l & 15;
    int t = threadIdx.x;

    __shared__ float xr[PDIM];
    if (t < PDIM) {
        int py = t / 24, rem = t % 24, px = rem / 3, c = rem % 3;
        xr[t] = x[(((size_t)(b * 3 + c) * 128) + (gy * 8 + py)) * 128 + gx * 8 + px];
    }
    __syncthreads();

    const float* bias = temb + (size_t)t_idx[b] * HD;
    for (int col = t; col < HD; col += 256) {
        float s = 0.f;
        #pragma unroll 4
        for (int k = 0; k < PDIM; k++) s += xr[k] * pw[(size_t)k * HD + col];
        g_h[(size_t)r * HD + col] = s + bias[col];
    }
}

// ---------------------------------------------------------------------------
// RMSNorm: one block per row of 768.
// ---------------------------------------------------------------------------
__global__ void rmsnorm_kernel(const float* __restrict__ in,
                               const float* __restrict__ w,
                               float* __restrict__ outp) {
    int r = blockIdx.x, t = threadIdx.x;
    const float* row = in + (size_t)r * HD;
    float v0 = row[t], v1 = row[t + 256], v2 = row[t + 512];
    float ss = v0 * v0 + v1 * v1 + v2 * v2;

    __shared__ float red[256];
    red[t] = ss; __syncthreads();
    for (int o = 128; o > 0; o >>= 1) {
        if (t < o) red[t] += red[t + o];
        __syncthreads();
    }
    float rms = sqrtf(red[0] * (1.0f / HD));
    float inv = 1.f / (rms + 1e-6f);

    float* orow = outp + (size_t)r * HD;
    orow[t]       = v0 * inv * w[t];
    orow[t + 256] = v1 * inv * w[t + 256];
    orow[t + 512] = v2 * inv * w[t + 512];
}

// ---------------------------------------------------------------------------
// Activation: silu on u|v (cols 0..3071 in place), RoPE on q,k (cols 3072..3327).
// One block per row.
// ---------------------------------------------------------------------------
__global__ void act_kernel(float* __restrict__ uvqk) {
    int r = blockIdx.x, t = threadIdx.x;
    float* row = uvqk + (size_t)r * UVQK;

    #pragma unroll
    for (int i = 0; i < 12; i++) {
        int c = t + i * 256;
        float v = row[c];
        row[c] = v / (1.f + expf(-v));
    }

    if (t < 64) {
        int l = r & 255;
        float p1 = (float)(l >> 4), p2 = (float)(l & 15);
        int j = t;
        int jj = (j < 32) ? j : j - 32;
        // freqs[i] = exp(-ln(1000) * i / 31)
        float f  = expf(-6.907755278982137f * (float)jj * (1.0f / 31.0f));
        float a1 = p1 * f, a2 = p2 * f;
        // pe = [sin(p1 f),cos(p1 f) | sin(p2 f),cos(p2 f)]; apply_rope uses
        // sin = pe[:64] (emb1), cos = pe[64:] (emb2).
        float sv = (j < 32) ? sinf(a1) : cosf(a1);
        float cv = (j < 32) ? sinf(a2) : cosf(a2);

        float q1 = row[3072 + j], q2 = row[3136 + j];
        row[3072 + j] = q1 * cv - q2 * sv;
        row[3136 + j] = q2 * cv + q1 * sv;

        float k1 = row[3200 + j], k2 = row[3264 + j];
        row[3200 + j] = k1 * cv - k2 * sv;
        row[3264 + j] = k2 * cv + k1 * sv;
    }
}

// ---------------------------------------------------------------------------
// Attention scores + softmax. One block per query row; thread t owns key t.
// ---------------------------------------------------------------------------
__global__ void attn_kernel(const float* __restrict__ uvqk, float* __restrict__ attn) {
    int r = blockIdx.x;             // query row, 0..4095
    int b = r >> 8;
    int t = threadIdx.x;            // key index, 0..255

    __shared__ float qs[KDIM];
    __shared__ float red[256];
    const float* qrow = uvqk + (size_t)r * UVQK + 3072;
    if (t < KDIM) qs[t] = qrow[t];
    __syncthreads();

    const float* krow = uvqk + (size_t)(b * 256 + t) * UVQK + 3200;
    float s = 0.f;
    #pragma unroll 8
    for (int j = 0; j < KDIM; j++) s += qs[j] * krow[j];
    s *= 0.08838834764831845f;      // K^(-1/2)

    red[t] = s; __syncthreads();
    for (int o = 128; o > 0; o >>= 1) {
        if (t < o) red[t] = fmaxf(red[t], red[t + o]);
        __syncthreads();
    }
    float mx = red[0];
    __syncthreads();

    float e = expf(s - mx);
    red[t] = e; __syncthreads();
    for (int o = 128; o > 0; o >>= 1) {
        if (t < o) red[t] += red[t + o];
        __syncthreads();
    }
    float inv = 1.f / red[0];
    attn[(size_t)r * 256 + t] = e * inv;
}

// ---------------------------------------------------------------------------
// o = u * av (elementwise), one block per row.
// ---------------------------------------------------------------------------
__global__ void mul_kernel() {
    int r = blockIdx.x, t = threadIdx.x;
    float* av = g_av + (size_t)r * ED;
    const float* u = g_uvqk + (size_t)r * UVQK;
    #pragma unroll
    for (int i = 0; i < 6; i++) {
        int c = t + i * 256;
        av[c] *= u[c];
    }
}

// ---------------------------------------------------------------------------
// Generic fp32 SGEMM: C[M,N] = A[M,K] * B[K,N] (+= if ACC).
// 128x128 tile, BK=16, 256 threads, 8x8 per thread. Requires M%128==0,
// N%128==0, K%16==0, all lds multiples of 4. grid.z = batch with strides.
// ---------------------------------------------------------------------------
template <bool ACC>
__global__ void sgemm_kernel(const float* __restrict__ A,
                             const float* __restrict__ B,
                             float* __restrict__ C,
                             int M, int N, int K, int lda, int ldb, int ldc,
                             long sA, long sB, long sC) {
    A += (long)blockIdx.z * sA;
    B += (long)blockIdx.z * sB;
    C += (long)blockIdx.z * sC;

    __shared__ float As[16][128];
    __shared__ float Bs[16][128];

    int t = threadIdx.x;
    int bm0 = blockIdx.y * 128, bn0 = blockIdx.x * 128;
    int ty = t >> 4, tx = t & 15;

    float acc[8][8] = {};

    int arow = t >> 2, ak4 = (t & 3) * 4;   // A: 64 rows x 16 K per pass
    int brow = t >> 5, bn4 = (t & 31) * 4;  // B: 8 K-rows x 128 N per pass

    for (int kt = 0; kt < K; kt += 16) {
        #pragma unroll
        for (int p = 0; p < 2; p++) {
            float4 a = *(const float4*)&A[(size_t)(bm0 + arow + p * 64) * lda + kt + ak4];
            As[ak4 + 0][arow + p * 64] = a.x;
            As[ak4 + 1][arow + p * 64] = a.y;
            As[ak4 + 2][arow + p * 64] = a.z;
            As[ak4 + 3][arow + p * 64] = a.w;
        }
        #pragma unroll
        for (int p = 0; p < 2; p++) {
            float4 bv = *(const float4*)&B[(size_t)(kt + brow + p * 8) * ldb + bn0 + bn4];
            *(float4*)&Bs[brow + p * 8][bn4] = bv;
        }
        __syncthreads();

        #pragma unroll
        for (int kk = 0; kk < 16; kk++) {
            float a[8], b[8];
            *(float4*)&a[0] = *(const float4*)&As[kk][ty * 8];
            *(float4*)&a[4] = *(const float4*)&As[kk][ty * 8 + 4];
            *(float4*)&b[0] = *(const float4*)&Bs[kk][tx * 8];
            *(float4*)&b[4] = *(const float4*)&Bs[kk][tx * 8 + 4];
            #pragma unroll
            for (int i = 0; i < 8; i++)
                #pragma unroll
                for (int j = 0; j < 8; j++)
                    acc[i][j] += a[i] * b[j];
        }
        __syncthreads();
    }

    #pragma unroll
    for (int i = 0; i < 8; i++) {
        float* crow = &C[(size_t)(bm0 + ty * 8 + i) * ldc + bn0 + tx * 8];
        if (ACC) {
            #pragma unroll
            for (int j = 0; j < 8; j++) crow[j] += acc[i][j];
        } else {
            float4 c0 = {acc[i][0], acc[i][1], acc[i][2], acc[i][3]};
            float4 c1 = {acc[i][4], acc[i][5], acc[i][6], acc[i][7]};
            *(float4*)&crow[0] = c0;
            *(float4*)&crow[4] = c1;
        }
    }
}

// ---------------------------------------------------------------------------
// Final unpatch: rmsnorm'd h (g_xn) @ unpatch_W, scattered to (B,3,128,128).
// One block per token row; threads 0..191 each own one PD column.
// ---------------------------------------------------------------------------
__global__ void unpatch_kernel(const float* __restrict__ uw, float* __restrict__ out) {
    int r = blockIdx.x, t = threadIdx.x;
    int b = r >> 8, l = r & 255, gy = l >> 4, gx = l & 15;

    __shared__ float xr[HD];
    const float* row = g_xn + (size_t)r * HD;
    xr[t] = row[t]; xr[t + 256] = row[t + 256]; xr[t + 512] = row[t + 512];
    __syncthreads();

    if (t < PDIM) {
        float s = 0.f;
        #pragma unroll 4
        for (int k = 0; k < HD; k++) s += xr[k] * uw[(size_t)k * PDIM + t];
        int py = t / 24, rem = t % 24, px = rem / 3, c = rem % 3;
        out[(((size_t)(b * 3 + c) * 128) + (gy * 8 + py)) * 128 + gx * 8 + px] = s;
    }
}

// ---------------------------------------------------------------------------
// Host launcher (graph-capturable: kernel launches on default stream only).
// ---------------------------------------------------------------------------
extern "C" void kernel_launch(void* const* d_in, const int* in_sizes, int n_in,
                              void* d_out, int out_size) {
    const float* x        = (const float*)d_in[0];
    const int*   t_idx    = (const int*)  d_in[1];
    const float* patch_W  = (const float*)d_in[2];
    const float* t_emb    = (const float*)d_in[3];
    const float* Wuv      = (const float*)d_in[4];
    const float* Wout     = (const float*)d_in[5];
    const float* gnorm    = (const float*)d_in[6];
    const float* fnorm_w  = (const float*)d_in[7];
    const float* unpatchW = (const float*)d_in[8];
    float* out = (float*)d_out;

    float *h, *xn, *uvqk, *attn, *av;
    cudaGetSymbolAddress((void**)&h,    g_h);
    cudaGetSymbolAddress((void**)&xn,   g_xn);
    cudaGetSymbolAddress((void**)&uvqk, g_uvqk);
    cudaGetSymbolAddress((void**)&attn, g_attn);
    cudaGetSymbolAddress((void**)&av,   g_av);

    patch_kernel<<<ROWS, 256>>>(x, t_idx, patch_W, t_emb);

    for (int l = 0; l < NLAYERS; l++) {
        rmsnorm_kernel<<<ROWS, 256>>>(h, gnorm + (size_t)l * HD, xn);

        // uvqk = xn @ Wuv[l] : (4096 x 768) * (768 x 3328)
        sgemm_kernel<false><<<dim3(UVQK / 128, ROWS / 128, 1), 256>>>(
            xn, Wuv + (size_t)l * HD * UVQK, uvqk,
            ROWS, UVQK, HD, HD, UVQK, UVQK, 0, 0, 0);

        act_kernel<<<ROWS, 256>>>(uvqk);
        attn_kernel<<<ROWS, 256>>>(uvqk, attn);

        // av = attn @ v : per-batch (256 x 256) * (256 x 1536)
        sgemm_kernel<false><<<dim3(ED / 128, LTOK / 128, NB), 256>>>(
            attn, uvqk + ED, av,
            LTOK, ED, LTOK, LTOK, UVQK, ED,
            (long)LTOK * LTOK, (long)LTOK * UVQK, (long)LTOK * ED);

        mul_kernel<<<ROWS, 256>>>();

        // h += (u*av) @ Wout[l] : (4096 x 1536) * (1536 x 768)
        sgemm_kernel<true><<<dim3(HD / 128, ROWS / 128, 1), 256>>>(
            av, Wout + (size_t)l * ED * HD, h,
            ROWS, HD, ED, ED, HD, HD, 0, 0, 0);
    }

    rmsnorm_kernel<<<ROWS, 256>>>(h, fnorm_w, xn);
    unpatch_kernel<<<ROWS, 256>>>(unpatchW, out);
}